// round 8
// baseline (speedup 1.0000x reference)
#include <cuda_runtime.h>
#include <stdint.h>

#define BLK 128

// ---------------- packed fp32x2 helpers (sm_103a FFMA2 path) ----------------
typedef unsigned long long u64;

__device__ __forceinline__ void lds_v2u64(unsigned addr, u64 &a, u64 &b) {
  asm volatile("ld.shared.v2.u64 {%0,%1}, [%2];" : "=l"(a), "=l"(b) : "r"(addr));
}
__device__ __forceinline__ void fma2(u64 &d, u64 a, u64 b) {
  asm("fma.rn.f32x2 %0, %1, %2, %0;" : "+l"(d) : "l"(a), "l"(b));
}
__device__ __forceinline__ u64 splat2(float v) {
  u64 r; asm("mov.b64 %0, {%1,%1};" : "=l"(r) : "f"(v)); return r;
}
__device__ __forceinline__ u64 pack2(float a, float b) {
  u64 r; asm("mov.b64 %0, {%1,%2};" : "=l"(r) : "f"(a), "f"(b)); return r;
}
__device__ __forceinline__ void unpack2(u64 v, float &a, float &b) {
  asm("mov.b64 {%0,%1}, %2;" : "=f"(a), "=f"(b) : "l"(v));
}
__device__ __forceinline__ float lo2(u64 v) {
  float a, b; unpack2(v, a, b); return a;
}

// ---------------- XLA/Eigen-exact f32 tanh ----------------
// Matches XLA ElementalIrEmitter::EmitTanh:
// |x| < 0.0004 -> x; else clamp to +-7.90531110763549805 and rational approx.
__device__ __forceinline__ float xtanh(float x) {
  float xc = fminf(fmaxf(x, -7.90531110763549805f), 7.90531110763549805f);
  float x2 = xc * xc;
  float p = fmaf(x2, -2.76076847742355e-16f, 2.00018790482477e-13f);
  p = fmaf(x2, p, -8.60467152213735e-10f);
  p = fmaf(x2, p,  5.12229709037114e-08f);
  p = fmaf(x2, p,  1.48572235717979e-05f);
  p = fmaf(x2, p,  6.37261928875436e-04f);
  p = fmaf(x2, p,  4.89352455891786e-03f);
  p = xc * p;
  float q = fmaf(x2, 1.19825839466702e-06f, 1.18534705686654e-04f);
  q = fmaf(x2, q, 2.26843463243900e-03f);
  q = fmaf(x2, q, 4.89352518554385e-03f);
  float r = __fdiv_rn(p, q);
  return (fabsf(x) < 0.0004f) ? x : r;
}

// XLA lowers lax.logistic as 0.5 + 0.5*tanh(0.5*x). 0.5*t is exact-scaled, so
// contraction here is rounding-neutral.
__device__ __forceinline__ float sigm(float x){ return 0.5f + 0.5f * xtanh(0.5f * x); }

// ---------------- threefry2x32 (exact JAX algorithm) ----------------
__device__ __forceinline__ unsigned rotl_(unsigned v, int r){ return (v<<r)|(v>>(32-r)); }

__device__ __forceinline__ void tf2x32(unsigned k0, unsigned k1, unsigned x0, unsigned x1,
                                       unsigned &o0, unsigned &o1) {
  unsigned k2 = k0 ^ k1 ^ 0x1BD11BDAu;
  x0 += k0; x1 += k1;
#define R4A x0+=x1; x1=rotl_(x1,13); x1^=x0; x0+=x1; x1=rotl_(x1,15); x1^=x0; \
            x0+=x1; x1=rotl_(x1,26); x1^=x0; x0+=x1; x1=rotl_(x1, 6); x1^=x0;
#define R4B x0+=x1; x1=rotl_(x1,17); x1^=x0; x0+=x1; x1=rotl_(x1,29); x1^=x0; \
            x0+=x1; x1=rotl_(x1,16); x1^=x0; x0+=x1; x1=rotl_(x1,24); x1^=x0;
  R4A x0+=k1; x1+=k2+1u;
  R4B x0+=k2; x1+=k0+2u;
  R4A x0+=k0; x1+=k1+3u;
  R4B x0+=k1; x1+=k2+4u;
  R4A x0+=k2; x1+=k0+5u;
#undef R4A
#undef R4B
  o0 = x0; o1 = x1;
}

// JAX uniform(tiny, 1) -> gumbel.  (1 - tiny) rounds to 1.0f, so the XLA
// f*(max-min)+min collapses to one rounded add of tiny.
__device__ __forceinline__ float gumbel_from_bits(unsigned bits){
  float f = __uint_as_float((bits >> 9) | 0x3f800000u) - 1.0f;
  const float tiny = 1.17549435e-38f;
  float u = fmaxf(__fadd_rn(f, tiny), tiny);
  return -logf(-logf(u));
}

// Shared layout (floats):
//   sWh   [0,     12288)   Wh 64x192           (also staging for Win tiles)
//   sWo   [12288, 14080)   W_out padded 64x28 (zeros in cols 26,27)
//   sWx   [14080, 14656)   Wx 3x192
//   sbx   [14656, 14848)
//   sbh   [14848, 15040)
//   sbo   [15040, 15068)   b_out padded to 28
//   set   [15068, 15152)   embed_table 28x3
//   skeys [15152, 15202)   25 step keys (2 u32 each)
#define SMEM_FLOATS 15202

__global__ void __launch_bounds__(BLK)
actor_kernel(const float* __restrict__ emb,  const float* __restrict__ etab,
             const float* __restrict__ Win,  const float* __restrict__ bin,
             const float* __restrict__ Wxg,  const float* __restrict__ Whg,
             const float* __restrict__ bxg,  const float* __restrict__ bhg,
             const float* __restrict__ Wog,  const float* __restrict__ bog,
             float* __restrict__ out, int B)
{
  extern __shared__ float sm[];
  float* sWh = sm;
  float* sWo = sm + 12288;
  float* sWx = sm + 14080;
  float* sbx = sm + 14656;
  float* sbh = sm + 14848;
  float* sbo = sm + 15040;
  float* set = sm + 15068;
  unsigned* skeys = (unsigned*)(sm + 15152);

  const unsigned aWh = (unsigned)__cvta_generic_to_shared(sWh);
  const unsigned aWo = (unsigned)__cvta_generic_to_shared(sWo);

  const int tid = threadIdx.x;
  const int b = blockIdx.x * BLK + tid;

  // ---- cooperative load of small weights ----
  for (int i = tid; i < 1792; i += BLK) {
    int r = i / 28, c = i - r * 28;
    sWo[i] = (c < 26) ? Wog[r * 26 + c] : 0.f;
  }
  for (int i = tid; i < 576; i += BLK) sWx[i] = Wxg[i];
  for (int i = tid; i < 192; i += BLK) { sbx[i] = bxg[i]; sbh[i] = bhg[i]; }
  if (tid < 28) sbo[tid] = (tid < 26) ? bog[tid] : 0.f;
  if (tid < 84) set[tid] = etab[tid];
  // step keys: partitionable (fold-like) split -> key_t = threefry((0,42),(0,t))
  if (tid < 25) {
    unsigned a, bq;
    tf2x32(0u, 42u, 0u, (unsigned)tid, a, bq);
    skeys[2*tid] = a; skeys[2*tid+1] = bq;
  }

  // ---- h0 = silu(emb @ Win + bin), Win staged through smem (reuse sWh) ----
  // Seed = bin (exact zeros) => identical to cublas serial-k accumulation.
  u64 accp[32];
  #pragma unroll
  for (int j = 0; j < 32; ++j) accp[j] = pack2(bin[2*j], bin[2*j+1]);
  const float4* erow = (const float4*)(emb + (long long)b * 512);
  #pragma unroll 1
  for (int tile = 0; tile < 8; ++tile) {
    __syncthreads();
    for (int i = tid; i < 4096; i += BLK) sWh[i] = Win[tile * 4096 + i];
    __syncthreads();
    #pragma unroll 1
    for (int k4 = 0; k4 < 16; ++k4) {
      float4 e = erow[tile * 16 + k4];
      #pragma unroll
      for (int kk = 0; kk < 4; ++kk) {
        float ekf = (kk == 0) ? e.x : (kk == 1) ? e.y : (kk == 2) ? e.z : e.w;
        u64 ek = splat2(ekf);
        unsigned base = aWh + (unsigned)((k4 * 4 + kk) * 64 * 4);
        #pragma unroll
        for (int j4 = 0; j4 < 16; ++j4) {
          u64 w0, w1;
          lds_v2u64(base + j4 * 16u, w0, w1);
          fma2(accp[2*j4+0], ek, w0);
          fma2(accp[2*j4+1], ek, w1);
        }
      }
    }
  }
  // hs[i] = splat2(silu(acc_i)) — h lives as 64 splat-packed f32x2 registers
  u64 hs[64];
  #pragma unroll
  for (int j = 0; j < 32; ++j) {
    float a, c; unpack2(accp[j], a, c);
    hs[2*j+0] = splat2(__fmul_rn(a, sigm(a)));
    hs[2*j+1] = splat2(__fmul_rn(c, sigm(c)));
  }

  __syncthreads();
  for (int i = tid; i < 12288; i += BLK) sWh[i] = Whg[i];
  __syncthreads();

  // ---- autoregressive loop ----
  int token = 26, done = 0;        // START=26
  float logp = 0.f;
  float nbuf[64], zbuf[64], larr[26], parr[26];   // local-mem scratch
  const unsigned base = (unsigned)b * 26u;
  float* msg  = out + (long long)b * 27;
  float* post = out + (long long)B * 28 + (long long)b * 650;
  float* msk  = out + (long long)B * 678 + (long long)b * 25;

  #pragma unroll 1
  for (int t = 0; t < 25; ++t) {
    float x0 = set[token*3+0], x1 = set[token*3+1], x2 = set[token*3+2];

    // fused gate pass: z (cols 0..63), r (64..127), hh (128..191), one h-stream.
    // h-accumulators seed with bh (exact zeros) => ha = h@Wh + bh grouping; the
    // x-part (xa = x@Wx + bx) is a separate chain joined by ONE add, matching
    // XLA's elementwise xa + ha.
    #pragma unroll 1
    for (int jq = 0; jq < 16; ++jq) {
      const int jz = 4*jq, jr = 64 + 4*jq, jh = 128 + 4*jq;
      u64 az0 = pack2(sbh[jz+0], sbh[jz+1]), az1 = pack2(sbh[jz+2], sbh[jz+3]);
      u64 ar0 = pack2(sbh[jr+0], sbh[jr+1]), ar1 = pack2(sbh[jr+2], sbh[jr+3]);
      u64 ah0 = pack2(sbh[jh+0], sbh[jh+1]), ah1 = pack2(sbh[jh+2], sbh[jh+3]);

      const unsigned bz = aWh + (unsigned)(jq * 16);          // (i*48 + jq)*16
      #pragma unroll
      for (int i = 0; i < 64; ++i) {
        u64 wz0, wz1, wr0, wr1, wh0, wh1;
        unsigned rowb = bz + (unsigned)(i * 48 * 16);
        lds_v2u64(rowb,            wz0, wz1);
        lds_v2u64(rowb + 16u*16u,  wr0, wr1);
        lds_v2u64(rowb + 32u*16u,  wh0, wh1);
        u64 hv = hs[i];
        fma2(az0, hv, wz0); fma2(az1, hv, wz1);
        fma2(ar0, hv, wr0); fma2(ar1, hv, wr1);
        fma2(ah0, hv, wh0); fma2(ah1, hv, wh1);
      }
      float hzv[4], hrv[4], hhv[4];
      unpack2(az0, hzv[0], hzv[1]); unpack2(az1, hzv[2], hzv[3]);
      unpack2(ar0, hrv[0], hrv[1]); unpack2(ar1, hrv[2], hrv[3]);
      unpack2(ah0, hhv[0], hhv[1]); unpack2(ah1, hhv[2], hhv[3]);
      #pragma unroll
      for (int u = 0; u < 4; ++u) {
        // x-dot chains: mul + fma + fma == serial k-order for K=3,
        // then + bx (exact zeros), then ONE add with the h-part.
        float xz = fmaf(x2, sWx[384+jz+u], fmaf(x1, sWx[192+jz+u], __fmul_rn(x0, sWx[jz+u])));
        xz = __fadd_rn(xz, sbx[jz+u]);
        float xr = fmaf(x2, sWx[384+jr+u], fmaf(x1, sWx[192+jr+u], __fmul_rn(x0, sWx[jr+u])));
        xr = __fadd_rn(xr, sbx[jr+u]);
        float xh = fmaf(x2, sWx[384+jh+u], fmaf(x1, sWx[192+jh+u], __fmul_rn(x0, sWx[jh+u])));
        xh = __fadd_rn(xh, sbx[jh+u]);
        zbuf[4*jq+u] = sigm(__fadd_rn(xz, hzv[u]));
        float r = sigm(__fadd_rn(xr, hrv[u]));
        // n = tanh(xh + r*hh): separate mul and add roundings (no contraction)
        nbuf[4*jq+u] = xtanh(__fadd_rn(xh, __fmul_rn(r, hhv[u])));
      }
    }
    // h' = z*h + (1-z)*n : mul, sub, mul, add — each rounded separately (XLA)
    #pragma unroll
    for (int j = 0; j < 64; ++j) {
      float z = zbuf[j];
      float hv = lo2(hs[j]);
      float hn = __fadd_rn(__fmul_rn(z, hv), __fmul_rn(__fsub_rn(1.0f, z), nbuf[j]));
      hs[j] = splat2(hn);
    }
    // logits = h @ Wout + bout (padded stride 28; bout exact zeros in seed)
    #pragma unroll 1
    for (int oq = 0; oq < 7; ++oq) {
      u64 a0 = pack2(sbo[4*oq+0], sbo[4*oq+1]);
      u64 a1 = pack2(sbo[4*oq+2], sbo[4*oq+3]);
      const unsigned bo = aWo + (unsigned)(oq * 16);
      #pragma unroll
      for (int i = 0; i < 64; ++i) {
        u64 w0, w1;
        lds_v2u64(bo + (unsigned)(i * 7 * 16), w0, w1);
        u64 hv = hs[i];
        fma2(a0, hv, w0); fma2(a1, hv, w1);
      }
      float v0, v1, v2, v3;
      unpack2(a0, v0, v1); unpack2(a1, v2, v3);
      int o = 4*oq;
      larr[o] = v0;
      if (o + 1 < 26) larr[o+1] = v1;
      if (o + 2 < 26) larr[o+2] = v2;
      if (o + 3 < 26) larr[o+3] = v3;
    }
    // softmax (continuous outputs only; sampling uses raw logits + gumbel)
    float m = larr[0];
    #pragma unroll 1
    for (int o = 1; o < 26; ++o) m = fmaxf(m, larr[o]);
    float s = 0.f;
    #pragma unroll 1
    for (int o = 0; o < 26; ++o) { float e = expf(larr[o] - m); parr[o] = e; s += e; }
    float invs = 1.0f / s;
    // gumbel-max categorical (partitionable threefry: bits = o0^o1 of (0, idx))
    unsigned kk0 = skeys[2*t], kk1 = skeys[2*t+1];
    float best = -3.4e38f; int samp = 0;
    #pragma unroll 2
    for (int o = 0; o < 26; ++o) {
      unsigned b0, b1;
      tf2x32(kk0, kk1, 0u, base + (unsigned)o, b0, b1);
      float y = __fadd_rn(larr[o], gumbel_from_bits(b0 ^ b1));
      if (y > best) { best = y; samp = o; }
    }
    float p = done ? 1.0f : parr[samp] * invs;
    int term = (samp == 25) ? 1 : 0;                 // END=25
    int tok_next = done ? 27 : (term ? 25 : samp);   // PAD=27
    int done_new = done | term;
    logp += logf(p);

    msg[1 + t] = (float)tok_next;
    msk[t] = (float)done_new;
    // posterior: 13 packed 8-byte streaming stores (write-once, evict-first)
    {
      float2* prow = (float2*)(post + t * 26);
      #pragma unroll 1
      for (int o2 = 0; o2 < 13; ++o2) {
        float2 v; v.x = parr[2*o2] * invs; v.y = parr[2*o2+1] * invs;
        __stcs(prow + o2, v);
      }
    }

    token = tok_next; done = done_new;
  }
  msg[0]  = 26.f;                       // START
  msg[26] = done ? 27.f : 25.f;         // final = done?PAD:END
  out[(long long)B * 27 + b] = logp;
}

extern "C" void kernel_launch(void* const* d_in, const int* in_sizes, int n_in,
                              void* d_out, int out_size) {
  const float* emb  = (const float*)d_in[0];
  const float* etab = (const float*)d_in[1];
  const float* Win  = (const float*)d_in[2];
  const float* bin  = (const float*)d_in[3];
  const float* Wx   = (const float*)d_in[4];
  const float* Wh   = (const float*)d_in[5];
  const float* bx   = (const float*)d_in[6];
  const float* bh   = (const float*)d_in[7];
  const float* Wo   = (const float*)d_in[8];
  const float* bo   = (const float*)d_in[9];
  float* out = (float*)d_out;
  int B = in_sizes[0] / 512;          // 32768

  int smem = SMEM_FLOATS * (int)sizeof(float);   // ~59.4 KB dynamic
  cudaFuncSetAttribute(actor_kernel, cudaFuncAttributeMaxDynamicSharedMemorySize, smem);
  actor_kernel<<<B / BLK, BLK, smem>>>(emb, etab, Win, bin, Wx, Wh, bx, bh, Wo, bo, out, B);
}